// round 15
// baseline (speedup 1.0000x reference)
#include <cuda_runtime.h>
#include <cuda_fp16.h>
#include <mma.h>
#include <cuda_pipeline.h>
#include <math.h>

using namespace nvcuda;

#define Bq   2
#define Nq   2048
#define Cq   1024
#define Hq   16
#define HDq  64
#define N3q  3072

// ---------------- scratch ----------------
__device__ __half g_xh[(size_t)Bq * Nq * Cq];
__device__ __half g_wqkvh[(size_t)N3q * Cq];
__device__ __half g_wprojh[(size_t)Cq * Cq];
__device__ __half g_qh[(size_t)Bq * Hq * Nq * HDq];
__device__ __half g_kh[(size_t)Bq * Hq * Nq * HDq];
__device__ __half g_vh[(size_t)Bq * Hq * Nq * HDq];
__device__ __half g_atth[(size_t)Bq * Nq * Cq];

// ---------------- fused fp32 -> fp16 (3 tensors, 1 launch) ----------------
__global__ __launch_bounds__(256) void cvt3_kernel(
    const float* __restrict__ a, __half* __restrict__ ah, int na4,
    const float* __restrict__ b, __half* __restrict__ bh, int nb4,
    const float* __restrict__ c, __half* __restrict__ ch, int nc4)
{
    int i = blockIdx.x * blockDim.x + threadIdx.x;
    const float* src;
    __half* dst;
    int j = i;
    if (j < na4) {
        src = a; dst = ah;
    } else if (j < na4 + nb4) {
        j -= na4; src = b; dst = bh;
    } else if (j < na4 + nb4 + nc4) {
        j -= na4 + nb4; src = c; dst = ch;
    } else {
        return;
    }
    float4 v = ((const float4*)src)[j];
    ((__half2*)dst)[2 * j]     = __floats2half2_rn(v.x, v.y);
    ((__half2*)dst)[2 * j + 1] = __floats2half2_rn(v.z, v.w);
}

// ---------------- GEMM prefetch (BK=64, 128 threads) ------
#define GSTG 9216   // 128*72 halves per matrix stage

__device__ __forceinline__ void gemm_prefetch64(
    __half* As, __half* Bs, const __half* A, const __half* W,
    int m0, int n0, int kk, int tid)
{
    #pragma unroll
    for (int i = 0; i < 8; i++) {
        const int c = tid + 128 * i;
        const int row = c >> 3;
        const int cq = c & 7;
        __pipeline_memcpy_async(As + row * 72 + cq * 8,
                                A + (size_t)(m0 + row) * Cq + kk + cq * 8, 16);
        __pipeline_memcpy_async(Bs + row * 72 + cq * 8,
                                W + (size_t)(n0 + row) * Cq + kk + cq * 8, 16);
    }
    __pipeline_commit();
}

// qkv scatter: one (row, col..col+1) fp32 pair
__device__ __forceinline__ void scatter_qkv(
    int row, int col, float v0, float v1, float* __restrict__ present)
{
    const int three = col >> 10;
    const int hh = (col >> 6) & 15;
    const int d  = col & 63;
    const int b  = row >> 11;
    const int nn = row & 2047;
    const size_t hidx = (((size_t)b * Hq + hh) * Nq + nn) * HDq + d;
    if (three == 0) {
        *(__half2*)&g_qh[hidx] = __floats2half2_rn(v0, v1);
    } else {
        const size_t pidx = ((((size_t)(three - 1) * Bq + b) * Hq + hh) * Nq + nn) * HDq + d;
        float2 pv; pv.x = v0; pv.y = v1;
        *(float2*)&present[pidx] = pv;
        if (three == 1) {
            *(__half2*)&g_kh[hidx] = __floats2half2_rn(v0, v1);
        } else {
            *(__half2*)&g_vh[hidx] = __floats2half2_rn(v0, v1);
        }
    }
}

// ---------------- wmma GEMM: qkv (64x64 warp tiles, frag double-buffer) ----
__global__ __launch_bounds__(128) void gemm_qkv_w(
    const __half* __restrict__ A, const __half* __restrict__ W,
    float* __restrict__ present)
{
    extern __shared__ __align__(16) char gsm[];
    __half* Abuf = (__half*)gsm;
    __half* Bbuf = Abuf + 2 * GSTG;

    const int tid  = threadIdx.x;
    const int lane = tid & 31;
    const int w    = tid >> 5;
    const int wm   = w >> 1;
    const int wn   = w & 1;
    const int m0   = blockIdx.y * 128;
    const int n0   = blockIdx.x * 128;

    wmma::fragment<wmma::accumulator, 16, 16, 16, float> acc[4][4];
    #pragma unroll
    for (int mt = 0; mt < 4; mt++) {
        #pragma unroll
        for (int nt = 0; nt < 4; nt++) {
            wmma::fill_fragment(acc[mt][nt], 0.0f);
        }
    }

    const int steps = Cq / 64;
    gemm_prefetch64(Abuf, Bbuf, A, W, m0, n0, 0, tid);

    for (int it = 0; it < steps; it++) {
        __pipeline_wait_prior(0);
        __syncthreads();
        if (it + 1 < steps) {
            const int st = (it + 1) & 1;
            gemm_prefetch64(Abuf + st * GSTG, Bbuf + st * GSTG, A, W,
                            m0, n0, (it + 1) * 64, tid);
        }

        const __half* As = Abuf + (it & 1) * GSTG;
        const __half* Bs = Bbuf + (it & 1) * GSTG;

        wmma::fragment<wmma::matrix_a, 16, 16, 16, __half, wmma::row_major> af[2][4];
        wmma::fragment<wmma::matrix_b, 16, 16, 16, __half, wmma::col_major> bf[2][4];
        #pragma unroll
        for (int mt = 0; mt < 4; mt++) {
            wmma::load_matrix_sync(af[0][mt], As + (wm * 64 + mt * 16) * 72, 72);
        }
        #pragma unroll
        for (int nt = 0; nt < 4; nt++) {
            wmma::load_matrix_sync(bf[0][nt], Bs + (wn * 64 + nt * 16) * 72, 72);
        }

        #pragma unroll
        for (int ks = 0; ks < 4; ks++) {
            const int cur = ks & 1;
            const int nxt = cur ^ 1;
            if (ks < 3) {
                #pragma unroll
                for (int mt = 0; mt < 4; mt++) {
                    wmma::load_matrix_sync(af[nxt][mt],
                        As + (wm * 64 + mt * 16) * 72 + (ks + 1) * 16, 72);
                }
                #pragma unroll
                for (int nt = 0; nt < 4; nt++) {
                    wmma::load_matrix_sync(bf[nxt][nt],
                        Bs + (wn * 64 + nt * 16) * 72 + (ks + 1) * 16, 72);
                }
            }
            #pragma unroll
            for (int mt = 0; mt < 4; mt++) {
                #pragma unroll
                for (int nt = 0; nt < 4; nt++) {
                    wmma::mma_sync(acc[mt][nt], af[cur][mt], bf[cur][nt], acc[mt][nt]);
                }
            }
        }
        __syncthreads();
    }

    // direct-from-fragment epilogue
    const int r0e = lane >> 2;
    const int cce = 2 * (lane & 3);
    #pragma unroll
    for (int mt = 0; mt < 4; mt++) {
        const int g0 = m0 + wm * 64 + mt * 16 + r0e;
        const int g1 = g0 + 8;
        #pragma unroll
        for (int nt = 0; nt < 4; nt++) {
            const float* x = acc[mt][nt].x;
            const int colA = n0 + wn * 64 + nt * 16 + cce;
            scatter_qkv(g0, colA,     x[0], x[1], present);
            scatter_qkv(g1, colA,     x[2], x[3], present);
            scatter_qkv(g0, colA + 8, x[4], x[5], present);
            scatter_qkv(g1, colA + 8, x[6], x[7], present);
        }
    }
}

// ---------------- wmma GEMM: proj (64x64 warp tiles, frag double-buffer) ----
__global__ __launch_bounds__(128) void gemm_proj_w(
    const __half* __restrict__ A, const __half* __restrict__ W,
    const float* __restrict__ bias, float* __restrict__ outp)
{
    extern __shared__ __align__(16) char gsm[];
    __half* Abuf = (__half*)gsm;
    __half* Bbuf = Abuf + 2 * GSTG;

    const int tid  = threadIdx.x;
    const int lane = tid & 31;
    const int w    = tid >> 5;
    const int wm   = w >> 1;
    const int wn   = w & 1;
    const int m0   = blockIdx.y * 128;
    const int n0   = blockIdx.x * 128;

    wmma::fragment<wmma::accumulator, 16, 16, 16, float> acc[4][4];
    #pragma unroll
    for (int mt = 0; mt < 4; mt++) {
        #pragma unroll
        for (int nt = 0; nt < 4; nt++) {
            wmma::fill_fragment(acc[mt][nt], 0.0f);
        }
    }

    const int steps = Cq / 64;
    gemm_prefetch64(Abuf, Bbuf, A, W, m0, n0, 0, tid);

    for (int it = 0; it < steps; it++) {
        __pipeline_wait_prior(0);
        __syncthreads();
        if (it + 1 < steps) {
            const int st = (it + 1) & 1;
            gemm_prefetch64(Abuf + st * GSTG, Bbuf + st * GSTG, A, W,
                            m0, n0, (it + 1) * 64, tid);
        }

        const __half* As = Abuf + (it & 1) * GSTG;
        const __half* Bs = Bbuf + (it & 1) * GSTG;

        wmma::fragment<wmma::matrix_a, 16, 16, 16, __half, wmma::row_major> af[2][4];
        wmma::fragment<wmma::matrix_b, 16, 16, 16, __half, wmma::col_major> bf[2][4];
        #pragma unroll
        for (int mt = 0; mt < 4; mt++) {
            wmma::load_matrix_sync(af[0][mt], As + (wm * 64 + mt * 16) * 72, 72);
        }
        #pragma unroll
        for (int nt = 0; nt < 4; nt++) {
            wmma::load_matrix_sync(bf[0][nt], Bs + (wn * 64 + nt * 16) * 72, 72);
        }

        #pragma unroll
        for (int ks = 0; ks < 4; ks++) {
            const int cur = ks & 1;
            const int nxt = cur ^ 1;
            if (ks < 3) {
                #pragma unroll
                for (int mt = 0; mt < 4; mt++) {
                    wmma::load_matrix_sync(af[nxt][mt],
                        As + (wm * 64 + mt * 16) * 72 + (ks + 1) * 16, 72);
                }
                #pragma unroll
                for (int nt = 0; nt < 4; nt++) {
                    wmma::load_matrix_sync(bf[nxt][nt],
                        Bs + (wn * 64 + nt * 16) * 72 + (ks + 1) * 16, 72);
                }
            }
            #pragma unroll
            for (int mt = 0; mt < 4; mt++) {
                #pragma unroll
                for (int nt = 0; nt < 4; nt++) {
                    wmma::mma_sync(acc[mt][nt], af[cur][mt], bf[cur][nt], acc[mt][nt]);
                }
            }
        }
        __syncthreads();
    }

    // direct-from-fragment epilogue with bias
    const int r0e = lane >> 2;
    const int cce = 2 * (lane & 3);
    #pragma unroll
    for (int mt = 0; mt < 4; mt++) {
        const int g0 = m0 + wm * 64 + mt * 16 + r0e;
        const int g1 = g0 + 8;
        #pragma unroll
        for (int nt = 0; nt < 4; nt++) {
            const float* x = acc[mt][nt].x;
            const int colA = n0 + wn * 64 + nt * 16 + cce;
            const float bA0 = __ldg(&bias[colA]);
            const float bA1 = __ldg(&bias[colA + 1]);
            const float bB0 = __ldg(&bias[colA + 8]);
            const float bB1 = __ldg(&bias[colA + 9]);
            float2 o;
            o.x = x[0] + bA0; o.y = x[1] + bA1;
            *(float2*)&outp[(size_t)g0 * Cq + colA] = o;
            o.x = x[2] + bA0; o.y = x[3] + bA1;
            *(float2*)&outp[(size_t)g1 * Cq + colA] = o;
            o.x = x[4] + bB0; o.y = x[5] + bB1;
            *(float2*)&outp[(size_t)g0 * Cq + colA + 8] = o;
            o.x = x[6] + bB0; o.y = x[7] + bB1;
            *(float2*)&outp[(size_t)g1 * Cq + colA + 8] = o;
        }
    }
}

// ---------------- K/V staging (cp.async, one 64-row block, 128 threads) ----
__device__ __forceinline__ void stage_kv_async(
    __half* kd, __half* vd, const __half* Kg, const __half* Vg, int kb, int tid)
{
    #pragma unroll
    for (int i = 0; i < 4; i++) {
        const int c = tid + 128 * i;
        const int row = c >> 3;
        const int cq = c & 7;
        __pipeline_memcpy_async(kd + row * 72 + cq * 8,
                                Kg + (size_t)(kb + row) * HDq + cq * 8, 16);
        __pipeline_memcpy_async(vd + row * 72 + cq * 8,
                                Vg + (size_t)(kb + row) * HDq + cq * 8, 16);
    }
}

// ---------------- wmma flash attention (register softmax, O in fragments) --
__global__ __launch_bounds__(128) void attn_w(
    const int* __restrict__ pad, const int* __restrict__ cs_ptr)
{
    extern __shared__ __align__(16) char dsm[];
    __half* kbuf = (__half*)dsm;
    __half* vbuf = kbuf + 2 * 4608;
    __half* pst  = vbuf + 2 * 4608;
    float*  padf = (float*)(pst + 4 * 1280);
    int*    padcnt = (int*)(padf + 2 * 64);

    const int b  = blockIdx.z;
    const int h  = blockIdx.y;
    const int q0 = ((int)gridDim.x - 1 - (int)blockIdx.x) * 64;
    const int tid  = threadIdx.x;
    const int lane = tid & 31;
    const int w    = tid >> 5;
    const int cs   = *cs_ptr;

    const __half* Qg = g_qh + (((size_t)b * Hq + h) * Nq) * HDq;
    const __half* Kg = g_kh + (((size_t)b * Hq + h) * Nq) * HDq;
    const __half* Vg = g_vh + (((size_t)b * Hq + h) * Nq) * HDq;

    __half* qstage = pst;
    #pragma unroll
    for (int i = 0; i < 4; i++) {
        const int c = tid + 128 * i;
        const int row = c >> 3;
        const int cq = c & 7;
        *(uint4*)&qstage[row * 72 + cq * 8] =
            *(const uint4*)&Qg[(size_t)(q0 + row) * HDq + cq * 8];
    }
    __syncthreads();

    wmma::fragment<wmma::matrix_a, 16, 16, 16, __half, wmma::row_major> aQ[4];
    #pragma unroll
    for (int ks = 0; ks < 4; ks++) {
        wmma::load_matrix_sync(aQ[ks], &qstage[(w * 16) * 72 + ks * 16], 72);
    }
    __syncthreads();

    __half* pstw = pst + w * 1280;
    const int r0 = lane >> 2;
    const int r1 = r0 + 8;
    const int cc = 2 * (lane & 3);
    const int qi0 = q0 + w * 16 + r0;
    const int qi1 = q0 + w * 16 + r1;
    const float scale = 0.125f;

    wmma::fragment<wmma::accumulator, 16, 16, 16, float> ofrag[4];
    #pragma unroll
    for (int nt = 0; nt < 4; nt++) {
        wmma::fill_fragment(ofrag[nt], 0.0f);
    }
    float m0 = -1e30f, m1 = -1e30f;
    float l0 = 0.f, l1 = 0.f;

    int hiq = q0 + 64;
    if (cs > hiq) hiq = (cs < Nq) ? cs : Nq;
    const int nkb = (hiq + 63) >> 6;

    stage_kv_async(kbuf, vbuf, Kg, Vg, 0, tid);
    __pipeline_commit();
    if (tid < 64) {
        const int pv = __ldg(&pad[(size_t)b * Nq + tid]);
        padf[tid] = pv ? -1e30f : 0.f;
        const unsigned bm = __ballot_sync(0xffffffffu, pv != 0);
        if ((tid & 31) == 0) padcnt[tid >> 5] = __popc(bm);
    }

    for (int kbi = 0; kbi < nkb; kbi++) {
        const int buf = kbi & 1;
        const int kb = kbi * 64;

        if (kbi + 1 < nkb) {
            stage_kv_async(kbuf + (buf ^ 1) * 4608, vbuf + (buf ^ 1) * 4608,
                           Kg, Vg, kb + 64, tid);
            __pipeline_commit();
            if (tid < 64) {
                const int pv = __ldg(&pad[(size_t)b * Nq + kb + 64 + tid]);
                padf[(buf ^ 1) * 64 + tid] = pv ? -1e30f : 0.f;
                const unsigned bm = __ballot_sync(0xffffffffu, pv != 0);
                if ((tid & 31) == 0) padcnt[(buf ^ 1) * 2 + (tid >> 5)] = __popc(bm);
            }
            __pipeline_wait_prior(1);
        } else {
            __pipeline_wait_prior(0);
        }
        __syncthreads();

        const bool allpad = (padcnt[buf * 2] + padcnt[buf * 2 + 1]) == 64;
        if (!allpad) {
            const __half* ksm = kbuf + buf * 4608;
            const __half* vsm = vbuf + buf * 4608;
            const float* padfb = padf + buf * 64;

            wmma::fragment<wmma::accumulator, 16, 16, 16, float> sacc[4];
            #pragma unroll
            for (int nt = 0; nt < 4; nt++) {
                wmma::fill_fragment(sacc[nt], 0.0f);
                #pragma unroll
                for (int ks = 0; ks < 4; ks++) {
                    wmma::fragment<wmma::matrix_b, 16, 16, 16, __half, wmma::col_major> bK;
                    wmma::load_matrix_sync(bK, &ksm[(nt * 16) * 72 + ks * 16], 72);
                    wmma::mma_sync(sacc[nt], aQ[ks], bK, sacc[nt]);
                }
            }

            float tmax0 = -1e30f, tmax1 = -1e30f;
            #pragma unroll
            for (int nt = 0; nt < 4; nt++) {
                const int base = nt * 16;
                const int cA = kb + base + cc;
                const int cB = cA + 8;
                const float pA0 = padfb[base + cc];
                const float pA1 = padfb[base + cc + 1];
                const float pB0 = padfb[base + cc + 8];
                const float pB1 = padfb[base + cc + 9];
                float* x = sacc[nt].x;
                x[0] = ((cA     <= qi0) || (cA     < cs)) ? x[0] * scale + pA0 : -1e30f;
                x[1] = ((cA + 1 <= qi0) || (cA + 1 < cs)) ? x[1] * scale + pA1 : -1e30f;
                x[2] = ((cA     <= qi1) || (cA     < cs)) ? x[2] * scale + pA0 : -1e30f;
                x[3] = ((cA + 1 <= qi1) || (cA + 1 < cs)) ? x[3] * scale + pA1 : -1e30f;
                x[4] = ((cB     <= qi0) || (cB     < cs)) ? x[4] * scale + pB0 : -1e30f;
                x[5] = ((cB + 1 <= qi0) || (cB + 1 < cs)) ? x[5] * scale + pB1 : -1e30f;
                x[6] = ((cB     <= qi1) || (cB     < cs)) ? x[6] * scale + pB0 : -1e30f;
                x[7] = ((cB + 1 <= qi1) || (cB + 1 < cs)) ? x[7] * scale + pB1 : -1e30f;
                tmax0 = fmaxf(tmax0, fmaxf(fmaxf(x[0], x[1]), fmaxf(x[4], x[5])));
                tmax1 = fmaxf(tmax1, fmaxf(fmaxf(x[2], x[3]), fmaxf(x[6], x[7])));
            }
            tmax0 = fmaxf(tmax0, __shfl_xor_sync(0xffffffffu, tmax0, 1));
            tmax0 = fmaxf(tmax0, __shfl_xor_sync(0xffffffffu, tmax0, 2));
            tmax1 = fmaxf(tmax1, __shfl_xor_sync(0xffffffffu, tmax1, 1));
            tmax1 = fmaxf(tmax1, __shfl_xor_sync(0xffffffffu, tmax1, 2));

            const float mn0 = fmaxf(m0, tmax0);
            const float mn1 = fmaxf(m1, tmax1);
            const float corr0 = __expf(m0 - mn0);
            const float corr1 = __expf(m1 - mn1);
            m0 = mn0;
            m1 = mn1;

            float ls0 = 0.f, ls1 = 0.f;
            #pragma unroll
            for (int nt = 0; nt < 4; nt++) {
                float* x = sacc[nt].x;
                const float p0 = __expf(x[0] - mn0);
                const float p1 = __expf(x[1] - mn0);
                const float p2 = __expf(x[2] - mn1);
                const float p3 = __expf(x[3] - mn1);
                const float p4 = __expf(x[4] - mn0);
                const float p5 = __expf(x[5] - mn0);
                const float p6 = __expf(x[6] - mn1);
                const float p7 = __expf(x[7] - mn1);
                ls0 += (p0 + p1) + (p4 + p5);
                ls1 += (p2 + p3) + (p6 + p7);
                const int base = nt * 16 + cc;
                *(__half2*)&pstw[r0 * 80 + base]     = __floats2half2_rn(p0, p1);
                *(__half2*)&pstw[r1 * 80 + base]     = __floats2half2_rn(p2, p3);
                *(__half2*)&pstw[r0 * 80 + base + 8] = __floats2half2_rn(p4, p5);
                *(__half2*)&pstw[r1 * 80 + base + 8] = __floats2half2_rn(p6, p7);
            }
            ls0 += __shfl_xor_sync(0xffffffffu, ls0, 1);
            ls0 += __shfl_xor_sync(0xffffffffu, ls0, 2);
            ls1 += __shfl_xor_sync(0xffffffffu, ls1, 1);
            ls1 += __shfl_xor_sync(0xffffffffu, ls1, 2);
            l0 = l0 * corr0 + ls0;
            l1 = l1 * corr1 + ls1;

            __syncwarp();

            wmma::fragment<wmma::matrix_a, 16, 16, 16, __half, wmma::row_major> aP[4];
            #pragma unroll
            for (int ks = 0; ks < 4; ks++) {
                wmma::load_matrix_sync(aP[ks], pstw + ks * 16, 80);
            }

            #pragma unroll
            for (int nt = 0; nt < 4; nt++) {
                float* x = ofrag[nt].x;
                x[0] *= corr0; x[1] *= corr0; x[4] *= corr0; x[5] *= corr0;
                x[2] *= corr1; x[3] *= corr1; x[6] *= corr1; x[7] *= corr1;
            }
            #pragma unroll
            for (int ks = 0; ks < 4; ks++) {
                #pragma unroll
                for (int nt = 0; nt < 4; nt++) {
                    wmma::fragment<wmma::matrix_b, 16, 16, 16, __half, wmma::row_major> bV;
                    wmma::load_matrix_sync(bV, &vsm[(ks * 16) * 72 + nt * 16], 72);
                    wmma::mma_sync(ofrag[nt], aP[ks], bV, ofrag[nt]);
                }
            }
        }
        __syncthreads();
    }

    const float inv0 = 1.f / l0;
    const float inv1 = 1.f / l1;
    __half* out0 = g_atth + ((size_t)b * Nq + qi0) * Cq + h * HDq;
    __half* out1 = g_atth + ((size_t)b * Nq + qi1) * Cq + h * HDq;
    #pragma unroll
    for (int nt = 0; nt < 4; nt++) {
        const float* x = ofrag[nt].x;
        const int col = nt * 16 + cc;
        *(__half2*)&out0[col]     = __floats2half2_rn(x[0] * inv0, x[1] * inv0);
        *(__half2*)&out1[col]     = __floats2half2_rn(x[2] * inv1, x[3] * inv1);
        *(__half2*)&out0[col + 8] = __floats2half2_rn(x[4] * inv0, x[5] * inv0);
        *(__half2*)&out1[col + 8] = __floats2half2_rn(x[6] * inv1, x[7] * inv1);
    }
}

// ---------------- launch ----------------
extern "C" void kernel_launch(void* const* d_in, const int* in_sizes, int n_in,
                              void* d_out, int out_size) {
    const float* x      = (const float*)d_in[0];
    const int*   pad    = (const int*)d_in[1];
    const int*   cs     = (const int*)d_in[2];
    const float* w_qkv  = (const float*)d_in[3];
    const float* w_proj = (const float*)d_in[4];
    const float* b_proj = (const float*)d_in[5];

    float* out     = (float*)d_out;
    float* present = out + (size_t)Bq * Nq * Cq;

    __half* xh;     cudaGetSymbolAddress((void**)&xh, g_xh);
    __half* wqkvh;  cudaGetSymbolAddress((void**)&wqkvh, g_wqkvh);
    __half* wprojh; cudaGetSymbolAddress((void**)&wprojh, g_wprojh);
    __half* atth;   cudaGetSymbolAddress((void**)&atth, g_atth);

    const int gemm_smem = 2 * (2 * GSTG) * 2;                                 // 73728 B
    const int attn_smem = 4 * 4608 * 2 + 4 * 1280 * 2 + 2 * 64 * 4 + 16;      // 47632 B
    cudaFuncSetAttribute(gemm_qkv_w, cudaFuncAttributeMaxDynamicSharedMemorySize, gemm_smem);
    cudaFuncSetAttribute(gemm_proj_w, cudaFuncAttributeMaxDynamicSharedMemorySize, gemm_smem);
    cudaFuncSetAttribute(attn_w, cudaFuncAttributeMaxDynamicSharedMemorySize, attn_smem);

    {
        const int na4 = (Bq * Nq * Cq) / 4;
        const int nb4 = (N3q * Cq) / 4;
        const int nc4 = (Cq * Cq) / 4;
        const int tot = na4 + nb4 + nc4;
        cvt3_kernel<<<(tot + 255) / 256, 256>>>(x, xh, na4, w_qkv, wqkvh, nb4,
                                                w_proj, wprojh, nc4);
    }
    {
        dim3 grid(N3q / 128, (Bq * Nq) / 128);
        gemm_qkv_w<<<grid, 128, gemm_smem>>>(xh, wqkvh, present);
    }
    {
        dim3 grid(Nq / 64, Hq, Bq);
        attn_w<<<grid, 128, attn_smem>>>(pad, cs);
    }
    {
        dim3 grid(Cq / 128, (Bq * Nq) / 128);
        gemm_proj_w<<<grid, 128, gemm_smem>>>(atth, wprojh, b_proj, out);
    }
}

// round 16
// speedup vs baseline: 1.4720x; 1.4720x over previous
#include <cuda_runtime.h>
#include <cuda_fp16.h>
#include <mma.h>
#include <cuda_pipeline.h>
#include <math.h>

using namespace nvcuda;

#define Bq   2
#define Nq   2048
#define Cq   1024
#define Hq   16
#define HDq  64
#define N3q  3072

// ---------------- scratch ----------------
__device__ __half g_xh[(size_t)Bq * Nq * Cq];
__device__ __half g_wqkvh[(size_t)N3q * Cq];
__device__ __half g_wprojh[(size_t)Cq * Cq];
__device__ __half g_qh[(size_t)Bq * Hq * Nq * HDq];
__device__ __half g_kh[(size_t)Bq * Hq * Nq * HDq];
__device__ __half g_vh[(size_t)Bq * Hq * Nq * HDq];
__device__ __half g_atth[(size_t)Bq * Nq * Cq];

// ---------------- fused fp32 -> fp16 (3 tensors, 1 launch) ----------------
__global__ __launch_bounds__(256) void cvt3_kernel(
    const float* __restrict__ a, __half* __restrict__ ah, int na4,
    const float* __restrict__ b, __half* __restrict__ bh, int nb4,
    const float* __restrict__ c, __half* __restrict__ ch, int nc4)
{
    int i = blockIdx.x * blockDim.x + threadIdx.x;
    const float* src;
    __half* dst;
    int j = i;
    if (j < na4) {
        src = a; dst = ah;
    } else if (j < na4 + nb4) {
        j -= na4; src = b; dst = bh;
    } else if (j < na4 + nb4 + nc4) {
        j -= na4 + nb4; src = c; dst = ch;
    } else {
        return;
    }
    float4 v = ((const float4*)src)[j];
    ((__half2*)dst)[2 * j]     = __floats2half2_rn(v.x, v.y);
    ((__half2*)dst)[2 * j + 1] = __floats2half2_rn(v.z, v.w);
}

// ---------------- GEMM prefetch (BK=64, 128 threads) ------
#define GSTG 9216   // 128*72 halves per matrix stage

__device__ __forceinline__ void gemm_prefetch64(
    __half* As, __half* Bs, const __half* A, const __half* W,
    int m0, int n0, int kk, int tid)
{
    #pragma unroll
    for (int i = 0; i < 8; i++) {
        const int c = tid + 128 * i;
        const int row = c >> 3;
        const int cq = c & 7;
        __pipeline_memcpy_async(As + row * 72 + cq * 8,
                                A + (size_t)(m0 + row) * Cq + kk + cq * 8, 16);
        __pipeline_memcpy_async(Bs + row * 72 + cq * 8,
                                W + (size_t)(n0 + row) * Cq + kk + cq * 8, 16);
    }
    __pipeline_commit();
}

// qkv scatter: one (row, col..col+1) fp32 pair
__device__ __forceinline__ void scatter_qkv(
    int row, int col, float v0, float v1, float* __restrict__ present)
{
    const int three = col >> 10;
    const int hh = (col >> 6) & 15;
    const int d  = col & 63;
    const int b  = row >> 11;
    const int nn = row & 2047;
    const size_t hidx = (((size_t)b * Hq + hh) * Nq + nn) * HDq + d;
    if (three == 0) {
        *(__half2*)&g_qh[hidx] = __floats2half2_rn(v0, v1);
    } else {
        const size_t pidx = ((((size_t)(three - 1) * Bq + b) * Hq + hh) * Nq + nn) * HDq + d;
        float2 pv; pv.x = v0; pv.y = v1;
        *(float2*)&present[pidx] = pv;
        if (three == 1) {
            *(__half2*)&g_kh[hidx] = __floats2half2_rn(v0, v1);
        } else {
            *(__half2*)&g_vh[hidx] = __floats2half2_rn(v0, v1);
        }
    }
}

// ---------------- wmma GEMM: qkv (64x64 tiles, 3-stage, 1 barrier/iter) ----
__global__ __launch_bounds__(128) void gemm_qkv_w(
    const __half* __restrict__ A, const __half* __restrict__ W,
    float* __restrict__ present)
{
    extern __shared__ __align__(16) char gsm[];
    __half* Abuf = (__half*)gsm;            // 3 x GSTG
    __half* Bbuf = Abuf + 3 * GSTG;         // 3 x GSTG

    const int tid  = threadIdx.x;
    const int lane = tid & 31;
    const int w    = tid >> 5;
    const int wm   = w >> 1;
    const int wn   = w & 1;
    const int m0   = blockIdx.y * 128;
    const int n0   = blockIdx.x * 128;

    wmma::fragment<wmma::accumulator, 16, 16, 16, float> acc[4][4];
    #pragma unroll
    for (int mt = 0; mt < 4; mt++) {
        #pragma unroll
        for (int nt = 0; nt < 4; nt++) {
            wmma::fill_fragment(acc[mt][nt], 0.0f);
        }
    }

    const int steps = Cq / 64;
    gemm_prefetch64(Abuf, Bbuf, A, W, m0, n0, 0, tid);
    gemm_prefetch64(Abuf + GSTG, Bbuf + GSTG, A, W, m0, n0, 64, tid);

    int sidx = 0;
    for (int it = 0; it < steps; it++) {
        if (it + 1 < steps) {
            __pipeline_wait_prior(1);
        } else {
            __pipeline_wait_prior(0);
        }
        __syncthreads();
        if (it + 2 < steps) {
            int ps = sidx + 2; if (ps >= 3) ps -= 3;
            gemm_prefetch64(Abuf + ps * GSTG, Bbuf + ps * GSTG, A, W,
                            m0, n0, (it + 2) * 64, tid);
        }

        const __half* As = Abuf + sidx * GSTG;
        const __half* Bs = Bbuf + sidx * GSTG;

        wmma::fragment<wmma::matrix_a, 16, 16, 16, __half, wmma::row_major> af[2][4];
        wmma::fragment<wmma::matrix_b, 16, 16, 16, __half, wmma::col_major> bf[2][4];
        #pragma unroll
        for (int mt = 0; mt < 4; mt++) {
            wmma::load_matrix_sync(af[0][mt], As + (wm * 64 + mt * 16) * 72, 72);
        }
        #pragma unroll
        for (int nt = 0; nt < 4; nt++) {
            wmma::load_matrix_sync(bf[0][nt], Bs + (wn * 64 + nt * 16) * 72, 72);
        }

        #pragma unroll
        for (int ks = 0; ks < 4; ks++) {
            const int cur = ks & 1;
            const int nxt = cur ^ 1;
            if (ks < 3) {
                #pragma unroll
                for (int mt = 0; mt < 4; mt++) {
                    wmma::load_matrix_sync(af[nxt][mt],
                        As + (wm * 64 + mt * 16) * 72 + (ks + 1) * 16, 72);
                }
                #pragma unroll
                for (int nt = 0; nt < 4; nt++) {
                    wmma::load_matrix_sync(bf[nxt][nt],
                        Bs + (wn * 64 + nt * 16) * 72 + (ks + 1) * 16, 72);
                }
            }
            #pragma unroll
            for (int mt = 0; mt < 4; mt++) {
                #pragma unroll
                for (int nt = 0; nt < 4; nt++) {
                    wmma::mma_sync(acc[mt][nt], af[cur][mt], bf[cur][nt], acc[mt][nt]);
                }
            }
        }
        sidx++; if (sidx >= 3) sidx -= 3;
    }

    // direct-from-fragment epilogue
    const int r0e = lane >> 2;
    const int cce = 2 * (lane & 3);
    #pragma unroll
    for (int mt = 0; mt < 4; mt++) {
        const int g0 = m0 + wm * 64 + mt * 16 + r0e;
        const int g1 = g0 + 8;
        #pragma unroll
        for (int nt = 0; nt < 4; nt++) {
            const float* x = acc[mt][nt].x;
            const int colA = n0 + wn * 64 + nt * 16 + cce;
            scatter_qkv(g0, colA,     x[0], x[1], present);
            scatter_qkv(g1, colA,     x[2], x[3], present);
            scatter_qkv(g0, colA + 8, x[4], x[5], present);
            scatter_qkv(g1, colA + 8, x[6], x[7], present);
        }
    }
}

// ---------------- wmma GEMM: proj (64x64 tiles, 3-stage, 1 barrier/iter) ---
__global__ __launch_bounds__(128) void gemm_proj_w(
    const __half* __restrict__ A, const __half* __restrict__ W,
    const float* __restrict__ bias, float* __restrict__ outp)
{
    extern __shared__ __align__(16) char gsm[];
    __half* Abuf = (__half*)gsm;
    __half* Bbuf = Abuf + 3 * GSTG;

    const int tid  = threadIdx.x;
    const int lane = tid & 31;
    const int w    = tid >> 5;
    const int wm   = w >> 1;
    const int wn   = w & 1;
    const int m0   = blockIdx.y * 128;
    const int n0   = blockIdx.x * 128;

    wmma::fragment<wmma::accumulator, 16, 16, 16, float> acc[4][4];
    #pragma unroll
    for (int mt = 0; mt < 4; mt++) {
        #pragma unroll
        for (int nt = 0; nt < 4; nt++) {
            wmma::fill_fragment(acc[mt][nt], 0.0f);
        }
    }

    const int steps = Cq / 64;
    gemm_prefetch64(Abuf, Bbuf, A, W, m0, n0, 0, tid);
    gemm_prefetch64(Abuf + GSTG, Bbuf + GSTG, A, W, m0, n0, 64, tid);

    int sidx = 0;
    for (int it = 0; it < steps; it++) {
        if (it + 1 < steps) {
            __pipeline_wait_prior(1);
        } else {
            __pipeline_wait_prior(0);
        }
        __syncthreads();
        if (it + 2 < steps) {
            int ps = sidx + 2; if (ps >= 3) ps -= 3;
            gemm_prefetch64(Abuf + ps * GSTG, Bbuf + ps * GSTG, A, W,
                            m0, n0, (it + 2) * 64, tid);
        }

        const __half* As = Abuf + sidx * GSTG;
        const __half* Bs = Bbuf + sidx * GSTG;

        wmma::fragment<wmma::matrix_a, 16, 16, 16, __half, wmma::row_major> af[2][4];
        wmma::fragment<wmma::matrix_b, 16, 16, 16, __half, wmma::col_major> bf[2][4];
        #pragma unroll
        for (int mt = 0; mt < 4; mt++) {
            wmma::load_matrix_sync(af[0][mt], As + (wm * 64 + mt * 16) * 72, 72);
        }
        #pragma unroll
        for (int nt = 0; nt < 4; nt++) {
            wmma::load_matrix_sync(bf[0][nt], Bs + (wn * 64 + nt * 16) * 72, 72);
        }

        #pragma unroll
        for (int ks = 0; ks < 4; ks++) {
            const int cur = ks & 1;
            const int nxt = cur ^ 1;
            if (ks < 3) {
                #pragma unroll
                for (int mt = 0; mt < 4; mt++) {
                    wmma::load_matrix_sync(af[nxt][mt],
                        As + (wm * 64 + mt * 16) * 72 + (ks + 1) * 16, 72);
                }
                #pragma unroll
                for (int nt = 0; nt < 4; nt++) {
                    wmma::load_matrix_sync(bf[nxt][nt],
                        Bs + (wn * 64 + nt * 16) * 72 + (ks + 1) * 16, 72);
                }
            }
            #pragma unroll
            for (int mt = 0; mt < 4; mt++) {
                #pragma unroll
                for (int nt = 0; nt < 4; nt++) {
                    wmma::mma_sync(acc[mt][nt], af[cur][mt], bf[cur][nt], acc[mt][nt]);
                }
            }
        }
        sidx++; if (sidx >= 3) sidx -= 3;
    }

    // direct-from-fragment epilogue with bias
    const int r0e = lane >> 2;
    const int cce = 2 * (lane & 3);
    #pragma unroll
    for (int mt = 0; mt < 4; mt++) {
        const int g0 = m0 + wm * 64 + mt * 16 + r0e;
        const int g1 = g0 + 8;
        #pragma unroll
        for (int nt = 0; nt < 4; nt++) {
            const float* x = acc[mt][nt].x;
            const int colA = n0 + wn * 64 + nt * 16 + cce;
            const float bA0 = __ldg(&bias[colA]);
            const float bA1 = __ldg(&bias[colA + 1]);
            const float bB0 = __ldg(&bias[colA + 8]);
            const float bB1 = __ldg(&bias[colA + 9]);
            float2 o;
            o.x = x[0] + bA0; o.y = x[1] + bA1;
            *(float2*)&outp[(size_t)g0 * Cq + colA] = o;
            o.x = x[2] + bA0; o.y = x[3] + bA1;
            *(float2*)&outp[(size_t)g1 * Cq + colA] = o;
            o.x = x[4] + bB0; o.y = x[5] + bB1;
            *(float2*)&outp[(size_t)g0 * Cq + colA + 8] = o;
            o.x = x[6] + bB0; o.y = x[7] + bB1;
            *(float2*)&outp[(size_t)g1 * Cq + colA + 8] = o;
        }
    }
}

// ---------------- K/V staging (cp.async, one 64-row block, 128 threads) ----
__device__ __forceinline__ void stage_kv_async(
    __half* kd, __half* vd, const __half* Kg, const __half* Vg, int kb, int tid)
{
    #pragma unroll
    for (int i = 0; i < 4; i++) {
        const int c = tid + 128 * i;
        const int row = c >> 3;
        const int cq = c & 7;
        __pipeline_memcpy_async(kd + row * 72 + cq * 8,
                                Kg + (size_t)(kb + row) * HDq + cq * 8, 16);
        __pipeline_memcpy_async(vd + row * 72 + cq * 8,
                                Vg + (size_t)(kb + row) * HDq + cq * 8, 16);
    }
}

// ---------------- wmma flash attention (register softmax, O in fragments) --
__global__ __launch_bounds__(128) void attn_w(
    const int* __restrict__ pad, const int* __restrict__ cs_ptr)
{
    extern __shared__ __align__(16) char dsm[];
    __half* kbuf = (__half*)dsm;
    __half* vbuf = kbuf + 2 * 4608;
    __half* pst  = vbuf + 2 * 4608;
    float*  padf = (float*)(pst + 4 * 1280);
    int*    padcnt = (int*)(padf + 2 * 64);

    const int b  = blockIdx.z;
    const int h  = blockIdx.y;
    const int q0 = ((int)gridDim.x - 1 - (int)blockIdx.x) * 64;
    const int tid  = threadIdx.x;
    const int lane = tid & 31;
    const int w    = tid >> 5;
    const int cs   = *cs_ptr;

    const __half* Qg = g_qh + (((size_t)b * Hq + h) * Nq) * HDq;
    const __half* Kg = g_kh + (((size_t)b * Hq + h) * Nq) * HDq;
    const __half* Vg = g_vh + (((size_t)b * Hq + h) * Nq) * HDq;

    __half* qstage = pst;
    #pragma unroll
    for (int i = 0; i < 4; i++) {
        const int c = tid + 128 * i;
        const int row = c >> 3;
        const int cq = c & 7;
        *(uint4*)&qstage[row * 72 + cq * 8] =
            *(const uint4*)&Qg[(size_t)(q0 + row) * HDq + cq * 8];
    }
    __syncthreads();

    wmma::fragment<wmma::matrix_a, 16, 16, 16, __half, wmma::row_major> aQ[4];
    #pragma unroll
    for (int ks = 0; ks < 4; ks++) {
        wmma::load_matrix_sync(aQ[ks], &qstage[(w * 16) * 72 + ks * 16], 72);
    }
    __syncthreads();

    __half* pstw = pst + w * 1280;
    const int r0 = lane >> 2;
    const int r1 = r0 + 8;
    const int cc = 2 * (lane & 3);
    const int qi0 = q0 + w * 16 + r0;
    const int qi1 = q0 + w * 16 + r1;
    const float scale = 0.125f;

    wmma::fragment<wmma::accumulator, 16, 16, 16, float> ofrag[4];
    #pragma unroll
    for (int nt = 0; nt < 4; nt++) {
        wmma::fill_fragment(ofrag[nt], 0.0f);
    }
    float m0 = -1e30f, m1 = -1e30f;
    float l0 = 0.f, l1 = 0.f;

    int hiq = q0 + 64;
    if (cs > hiq) hiq = (cs < Nq) ? cs : Nq;
    const int nkb = (hiq + 63) >> 6;

    stage_kv_async(kbuf, vbuf, Kg, Vg, 0, tid);
    __pipeline_commit();
    if (tid < 64) {
        const int pv = __ldg(&pad[(size_t)b * Nq + tid]);
        padf[tid] = pv ? -1e30f : 0.f;
        const unsigned bm = __ballot_sync(0xffffffffu, pv != 0);
        if ((tid & 31) == 0) padcnt[tid >> 5] = __popc(bm);
    }

    for (int kbi = 0; kbi < nkb; kbi++) {
        const int buf = kbi & 1;
        const int kb = kbi * 64;

        if (kbi + 1 < nkb) {
            stage_kv_async(kbuf + (buf ^ 1) * 4608, vbuf + (buf ^ 1) * 4608,
                           Kg, Vg, kb + 64, tid);
            __pipeline_commit();
            if (tid < 64) {
                const int pv = __ldg(&pad[(size_t)b * Nq + kb + 64 + tid]);
                padf[(buf ^ 1) * 64 + tid] = pv ? -1e30f : 0.f;
                const unsigned bm = __ballot_sync(0xffffffffu, pv != 0);
                if ((tid & 31) == 0) padcnt[(buf ^ 1) * 2 + (tid >> 5)] = __popc(bm);
            }
            __pipeline_wait_prior(1);
        } else {
            __pipeline_wait_prior(0);
        }
        __syncthreads();

        const bool allpad = (padcnt[buf * 2] + padcnt[buf * 2 + 1]) == 64;
        if (!allpad) {
            const __half* ksm = kbuf + buf * 4608;
            const __half* vsm = vbuf + buf * 4608;
            const float* padfb = padf + buf * 64;

            wmma::fragment<wmma::accumulator, 16, 16, 16, float> sacc[4];
            #pragma unroll
            for (int nt = 0; nt < 4; nt++) {
                wmma::fill_fragment(sacc[nt], 0.0f);
                #pragma unroll
                for (int ks = 0; ks < 4; ks++) {
                    wmma::fragment<wmma::matrix_b, 16, 16, 16, __half, wmma::col_major> bK;
                    wmma::load_matrix_sync(bK, &ksm[(nt * 16) * 72 + ks * 16], 72);
                    wmma::mma_sync(sacc[nt], aQ[ks], bK, sacc[nt]);
                }
            }

            float tmax0 = -1e30f, tmax1 = -1e30f;
            #pragma unroll
            for (int nt = 0; nt < 4; nt++) {
                const int base = nt * 16;
                const int cA = kb + base + cc;
                const int cB = cA + 8;
                const float pA0 = padfb[base + cc];
                const float pA1 = padfb[base + cc + 1];
                const float pB0 = padfb[base + cc + 8];
                const float pB1 = padfb[base + cc + 9];
                float* x = sacc[nt].x;
                x[0] = ((cA     <= qi0) || (cA     < cs)) ? x[0] * scale + pA0 : -1e30f;
                x[1] = ((cA + 1 <= qi0) || (cA + 1 < cs)) ? x[1] * scale + pA1 : -1e30f;
                x[2] = ((cA     <= qi1) || (cA     < cs)) ? x[2] * scale + pA0 : -1e30f;
                x[3] = ((cA + 1 <= qi1) || (cA + 1 < cs)) ? x[3] * scale + pA1 : -1e30f;
                x[4] = ((cB     <= qi0) || (cB     < cs)) ? x[4] * scale + pB0 : -1e30f;
                x[5] = ((cB + 1 <= qi0) || (cB + 1 < cs)) ? x[5] * scale + pB1 : -1e30f;
                x[6] = ((cB     <= qi1) || (cB     < cs)) ? x[6] * scale + pB0 : -1e30f;
                x[7] = ((cB + 1 <= qi1) || (cB + 1 < cs)) ? x[7] * scale + pB1 : -1e30f;
                tmax0 = fmaxf(tmax0, fmaxf(fmaxf(x[0], x[1]), fmaxf(x[4], x[5])));
                tmax1 = fmaxf(tmax1, fmaxf(fmaxf(x[2], x[3]), fmaxf(x[6], x[7])));
            }
            tmax0 = fmaxf(tmax0, __shfl_xor_sync(0xffffffffu, tmax0, 1));
            tmax0 = fmaxf(tmax0, __shfl_xor_sync(0xffffffffu, tmax0, 2));
            tmax1 = fmaxf(tmax1, __shfl_xor_sync(0xffffffffu, tmax1, 1));
            tmax1 = fmaxf(tmax1, __shfl_xor_sync(0xffffffffu, tmax1, 2));

            const float mn0 = fmaxf(m0, tmax0);
            const float mn1 = fmaxf(m1, tmax1);
            const float corr0 = __expf(m0 - mn0);
            const float corr1 = __expf(m1 - mn1);
            m0 = mn0;
            m1 = mn1;

            float ls0 = 0.f, ls1 = 0.f;
            #pragma unroll
            for (int nt = 0; nt < 4; nt++) {
                float* x = sacc[nt].x;
                const float p0 = __expf(x[0] - mn0);
                const float p1 = __expf(x[1] - mn0);
                const float p2 = __expf(x[2] - mn1);
                const float p3 = __expf(x[3] - mn1);
                const float p4 = __expf(x[4] - mn0);
                const float p5 = __expf(x[5] - mn0);
                const float p6 = __expf(x[6] - mn1);
                const float p7 = __expf(x[7] - mn1);
                ls0 += (p0 + p1) + (p4 + p5);
                ls1 += (p2 + p3) + (p6 + p7);
                const int base = nt * 16 + cc;
                *(__half2*)&pstw[r0 * 80 + base]     = __floats2half2_rn(p0, p1);
                *(__half2*)&pstw[r1 * 80 + base]     = __floats2half2_rn(p2, p3);
                *(__half2*)&pstw[r0 * 80 + base + 8] = __floats2half2_rn(p4, p5);
                *(__half2*)&pstw[r1 * 80 + base + 8] = __floats2half2_rn(p6, p7);
            }
            ls0 += __shfl_xor_sync(0xffffffffu, ls0, 1);
            ls0 += __shfl_xor_sync(0xffffffffu, ls0, 2);
            ls1 += __shfl_xor_sync(0xffffffffu, ls1, 1);
            ls1 += __shfl_xor_sync(0xffffffffu, ls1, 2);
            l0 = l0 * corr0 + ls0;
            l1 = l1 * corr1 + ls1;

            __syncwarp();

            wmma::fragment<wmma::matrix_a, 16, 16, 16, __half, wmma::row_major> aP[4];
            #pragma unroll
            for (int ks = 0; ks < 4; ks++) {
                wmma::load_matrix_sync(aP[ks], pstw + ks * 16, 80);
            }

            #pragma unroll
            for (int nt = 0; nt < 4; nt++) {
                float* x = ofrag[nt].x;
                x[0] *= corr0; x[1] *= corr0; x[4] *= corr0; x[5] *= corr0;
                x[2] *= corr1; x[3] *= corr1; x[6] *= corr1; x[7] *= corr1;
            }
            #pragma unroll
            for (int ks = 0; ks < 4; ks++) {
                #pragma unroll
                for (int nt = 0; nt < 4; nt++) {
                    wmma::fragment<wmma::matrix_b, 16, 16, 16, __half, wmma::row_major> bV;
                    wmma::load_matrix_sync(bV, &vsm[(ks * 16) * 72 + nt * 16], 72);
                    wmma::mma_sync(ofrag[nt], aP[ks], bV, ofrag[nt]);
                }
            }
        }
        __syncthreads();
    }

    const float inv0 = 1.f / l0;
    const float inv1 = 1.f / l1;
    __half* out0 = g_atth + ((size_t)b * Nq + qi0) * Cq + h * HDq;
    __half* out1 = g_atth + ((size_t)b * Nq + qi1) * Cq + h * HDq;
    #pragma unroll
    for (int nt = 0; nt < 4; nt++) {
        const float* x = ofrag[nt].x;
        const int col = nt * 16 + cc;
        *(__half2*)&out0[col]     = __floats2half2_rn(x[0] * inv0, x[1] * inv0);
        *(__half2*)&out1[col]     = __floats2half2_rn(x[2] * inv1, x[3] * inv1);
        *(__half2*)&out0[col + 8] = __floats2half2_rn(x[4] * inv0, x[5] * inv0);
        *(__half2*)&out1[col + 8] = __floats2half2_rn(x[6] * inv1, x[7] * inv1);
    }
}

// ---------------- launch ----------------
extern "C" void kernel_launch(void* const* d_in, const int* in_sizes, int n_in,
                              void* d_out, int out_size) {
    const float* x      = (const float*)d_in[0];
    const int*   pad    = (const int*)d_in[1];
    const int*   cs     = (const int*)d_in[2];
    const float* w_qkv  = (const float*)d_in[3];
    const float* w_proj = (const float*)d_in[4];
    const float* b_proj = (const float*)d_in[5];

    float* out     = (float*)d_out;
    float* present = out + (size_t)Bq * Nq * Cq;

    __half* xh;     cudaGetSymbolAddress((void**)&xh, g_xh);
    __half* wqkvh;  cudaGetSymbolAddress((void**)&wqkvh, g_wqkvh);
    __half* wprojh; cudaGetSymbolAddress((void**)&wprojh, g_wprojh);
    __half* atth;   cudaGetSymbolAddress((void**)&atth, g_atth);

    const int gemm_smem = 2 * (3 * GSTG) * 2;                                 // 110592 B
    const int attn_smem = 4 * 4608 * 2 + 4 * 1280 * 2 + 2 * 64 * 4 + 16;      // 47632 B
    cudaFuncSetAttribute(gemm_qkv_w, cudaFuncAttributeMaxDynamicSharedMemorySize, gemm_smem);
    cudaFuncSetAttribute(gemm_proj_w, cudaFuncAttributeMaxDynamicSharedMemorySize, gemm_smem);
    cudaFuncSetAttribute(attn_w, cudaFuncAttributeMaxDynamicSharedMemorySize, attn_smem);

    {
        const int na4 = (Bq * Nq * Cq) / 4;
        const int nb4 = (N3q * Cq) / 4;
        const int nc4 = (Cq * Cq) / 4;
        const int tot = na4 + nb4 + nc4;
        cvt3_kernel<<<(tot + 255) / 256, 256>>>(x, xh, na4, w_qkv, wqkvh, nb4,
                                                w_proj, wprojh, nc4);
    }
    {
        dim3 grid(N3q / 128, (Bq * Nq) / 128);
        gemm_qkv_w<<<grid, 128, gemm_smem>>>(xh, wqkvh, present);
    }
    {
        dim3 grid(Nq / 64, Hq, Bq);
        attn_w<<<grid, 128, attn_smem>>>(pad, cs);
    }
    {
        dim3 grid(Cq / 128, (Bq * Nq) / 128);
        gemm_proj_w<<<grid, 128, gemm_smem>>>(atth, wprojh, b_proj, out);
    }
}

// round 17
// speedup vs baseline: 1.5238x; 1.0352x over previous
#include <cuda_runtime.h>
#include <cuda_fp16.h>
#include <mma.h>
#include <cuda_pipeline.h>
#include <math.h>

using namespace nvcuda;

#define Bq   2
#define Nq   2048
#define Cq   1024
#define Hq   16
#define HDq  64
#define N3q  3072

// ---------------- scratch ----------------
__device__ __half g_xh[(size_t)Bq * Nq * Cq];
__device__ __half g_wqkvh[(size_t)N3q * Cq];
__device__ __half g_wprojh[(size_t)Cq * Cq];
__device__ __half g_qh[(size_t)Bq * Hq * Nq * HDq];
__device__ __half g_kh[(size_t)Bq * Hq * Nq * HDq];
__device__ __half g_vh[(size_t)Bq * Hq * Nq * HDq];
__device__ __half g_atth[(size_t)Bq * Nq * Cq];

// ---------------- fused fp32 -> fp16 (3 tensors, 1 launch) ----------------
__global__ __launch_bounds__(256) void cvt3_kernel(
    const float* __restrict__ a, __half* __restrict__ ah, int na4,
    const float* __restrict__ b, __half* __restrict__ bh, int nb4,
    const float* __restrict__ c, __half* __restrict__ ch, int nc4)
{
    int i = blockIdx.x * blockDim.x + threadIdx.x;
    const float* src;
    __half* dst;
    int j = i;
    if (j < na4) {
        src = a; dst = ah;
    } else if (j < na4 + nb4) {
        j -= na4; src = b; dst = bh;
    } else if (j < na4 + nb4 + nc4) {
        j -= na4 + nb4; src = c; dst = ch;
    } else {
        return;
    }
    float4 v = ((const float4*)src)[j];
    ((__half2*)dst)[2 * j]     = __floats2half2_rn(v.x, v.y);
    ((__half2*)dst)[2 * j + 1] = __floats2half2_rn(v.z, v.w);
}

// ---------------- GEMM prefetch (BK=64, 128 threads) ------
#define GSTG 9216   // 128*72 halves per matrix stage

__device__ __forceinline__ void gemm_prefetch64(
    __half* As, __half* Bs, const __half* A, const __half* W,
    int m0, int n0, int kk, int tid)
{
    #pragma unroll
    for (int i = 0; i < 8; i++) {
        const int c = tid + 128 * i;
        const int row = c >> 3;
        const int cq = c & 7;
        __pipeline_memcpy_async(As + row * 72 + cq * 8,
                                A + (size_t)(m0 + row) * Cq + kk + cq * 8, 16);
        __pipeline_memcpy_async(Bs + row * 72 + cq * 8,
                                W + (size_t)(n0 + row) * Cq + kk + cq * 8, 16);
    }
    __pipeline_commit();
}

// qkv scatter: one (row, col..col+1) fp32 pair
__device__ __forceinline__ void scatter_qkv(
    int row, int col, float v0, float v1, float* __restrict__ present)
{
    const int three = col >> 10;
    const int hh = (col >> 6) & 15;
    const int d  = col & 63;
    const int b  = row >> 11;
    const int nn = row & 2047;
    const size_t hidx = (((size_t)b * Hq + hh) * Nq + nn) * HDq + d;
    if (three == 0) {
        *(__half2*)&g_qh[hidx] = __floats2half2_rn(v0, v1);
    } else {
        const size_t pidx = ((((size_t)(three - 1) * Bq + b) * Hq + hh) * Nq + nn) * HDq + d;
        float2 pv; pv.x = v0; pv.y = v1;
        *(float2*)&present[pidx] = pv;
        if (three == 1) {
            *(__half2*)&g_kh[hidx] = __floats2half2_rn(v0, v1);
        } else {
            *(__half2*)&g_vh[hidx] = __floats2half2_rn(v0, v1);
        }
    }
}

// ---------------- wmma GEMM: qkv (64x64 tiles, 2-stage, 3 CTAs/SM) ----
__global__ __launch_bounds__(128, 3) void gemm_qkv_w(
    const __half* __restrict__ A, const __half* __restrict__ W,
    float* __restrict__ present)
{
    extern __shared__ __align__(16) char gsm[];
    __half* Abuf = (__half*)gsm;            // 2 x GSTG
    __half* Bbuf = Abuf + 2 * GSTG;         // 2 x GSTG

    const int tid  = threadIdx.x;
    const int lane = tid & 31;
    const int w    = tid >> 5;
    const int wm   = w >> 1;
    const int wn   = w & 1;
    const int m0   = blockIdx.y * 128;
    const int n0   = blockIdx.x * 128;

    wmma::fragment<wmma::accumulator, 16, 16, 16, float> acc[4][4];
    #pragma unroll
    for (int mt = 0; mt < 4; mt++) {
        #pragma unroll
        for (int nt = 0; nt < 4; nt++) {
            wmma::fill_fragment(acc[mt][nt], 0.0f);
        }
    }

    const int steps = Cq / 64;
    gemm_prefetch64(Abuf, Bbuf, A, W, m0, n0, 0, tid);

    for (int it = 0; it < steps; it++) {
        __pipeline_wait_prior(0);
        __syncthreads();
        if (it + 1 < steps) {
            const int st = (it + 1) & 1;
            gemm_prefetch64(Abuf + st * GSTG, Bbuf + st * GSTG, A, W,
                            m0, n0, (it + 1) * 64, tid);
        }

        const __half* As = Abuf + (it & 1) * GSTG;
        const __half* Bs = Bbuf + (it & 1) * GSTG;

        wmma::fragment<wmma::matrix_a, 16, 16, 16, __half, wmma::row_major> af[2][4];
        wmma::fragment<wmma::matrix_b, 16, 16, 16, __half, wmma::col_major> bf[2][4];
        #pragma unroll
        for (int mt = 0; mt < 4; mt++) {
            wmma::load_matrix_sync(af[0][mt], As + (wm * 64 + mt * 16) * 72, 72);
        }
        #pragma unroll
        for (int nt = 0; nt < 4; nt++) {
            wmma::load_matrix_sync(bf[0][nt], Bs + (wn * 64 + nt * 16) * 72, 72);
        }

        #pragma unroll
        for (int ks = 0; ks < 4; ks++) {
            const int cur = ks & 1;
            const int nxt = cur ^ 1;
            if (ks < 3) {
                #pragma unroll
                for (int mt = 0; mt < 4; mt++) {
                    wmma::load_matrix_sync(af[nxt][mt],
                        As + (wm * 64 + mt * 16) * 72 + (ks + 1) * 16, 72);
                }
                #pragma unroll
                for (int nt = 0; nt < 4; nt++) {
                    wmma::load_matrix_sync(bf[nxt][nt],
                        Bs + (wn * 64 + nt * 16) * 72 + (ks + 1) * 16, 72);
                }
            }
            #pragma unroll
            for (int mt = 0; mt < 4; mt++) {
                #pragma unroll
                for (int nt = 0; nt < 4; nt++) {
                    wmma::mma_sync(acc[mt][nt], af[cur][mt], bf[cur][nt], acc[mt][nt]);
                }
            }
        }
        __syncthreads();
    }

    // direct-from-fragment epilogue
    const int r0e = lane >> 2;
    const int cce = 2 * (lane & 3);
    #pragma unroll
    for (int mt = 0; mt < 4; mt++) {
        const int g0 = m0 + wm * 64 + mt * 16 + r0e;
        const int g1 = g0 + 8;
        #pragma unroll
        for (int nt = 0; nt < 4; nt++) {
            const float* x = acc[mt][nt].x;
            const int colA = n0 + wn * 64 + nt * 16 + cce;
            scatter_qkv(g0, colA,     x[0], x[1], present);
            scatter_qkv(g1, colA,     x[2], x[3], present);
            scatter_qkv(g0, colA + 8, x[4], x[5], present);
            scatter_qkv(g1, colA + 8, x[6], x[7], present);
        }
    }
}

// ---------------- wmma GEMM: proj (64x64 tiles, 2-stage, 3 CTAs/SM) ---------
__global__ __launch_bounds__(128, 3) void gemm_proj_w(
    const __half* __restrict__ A, const __half* __restrict__ W,
    const float* __restrict__ bias, float* __restrict__ outp)
{
    extern __shared__ __align__(16) char gsm[];
    __half* Abuf = (__half*)gsm;
    __half* Bbuf = Abuf + 2 * GSTG;

    const int tid  = threadIdx.x;
    const int lane = tid & 31;
    const int w    = tid >> 5;
    const int wm   = w >> 1;
    const int wn   = w & 1;
    const int m0   = blockIdx.y * 128;
    const int n0   = blockIdx.x * 128;

    wmma::fragment<wmma::accumulator, 16, 16, 16, float> acc[4][4];
    #pragma unroll
    for (int mt = 0; mt < 4; mt++) {
        #pragma unroll
        for (int nt = 0; nt < 4; nt++) {
            wmma::fill_fragment(acc[mt][nt], 0.0f);
        }
    }

    const int steps = Cq / 64;
    gemm_prefetch64(Abuf, Bbuf, A, W, m0, n0, 0, tid);

    for (int it = 0; it < steps; it++) {
        __pipeline_wait_prior(0);
        __syncthreads();
        if (it + 1 < steps) {
            const int st = (it + 1) & 1;
            gemm_prefetch64(Abuf + st * GSTG, Bbuf + st * GSTG, A, W,
                            m0, n0, (it + 1) * 64, tid);
        }

        const __half* As = Abuf + (it & 1) * GSTG;
        const __half* Bs = Bbuf + (it & 1) * GSTG;

        wmma::fragment<wmma::matrix_a, 16, 16, 16, __half, wmma::row_major> af[2][4];
        wmma::fragment<wmma::matrix_b, 16, 16, 16, __half, wmma::col_major> bf[2][4];
        #pragma unroll
        for (int mt = 0; mt < 4; mt++) {
            wmma::load_matrix_sync(af[0][mt], As + (wm * 64 + mt * 16) * 72, 72);
        }
        #pragma unroll
        for (int nt = 0; nt < 4; nt++) {
            wmma::load_matrix_sync(bf[0][nt], Bs + (wn * 64 + nt * 16) * 72, 72);
        }

        #pragma unroll
        for (int ks = 0; ks < 4; ks++) {
            const int cur = ks & 1;
            const int nxt = cur ^ 1;
            if (ks < 3) {
                #pragma unroll
                for (int mt = 0; mt < 4; mt++) {
                    wmma::load_matrix_sync(af[nxt][mt],
                        As + (wm * 64 + mt * 16) * 72 + (ks + 1) * 16, 72);
                }
                #pragma unroll
                for (int nt = 0; nt < 4; nt++) {
                    wmma::load_matrix_sync(bf[nxt][nt],
                        Bs + (wn * 64 + nt * 16) * 72 + (ks + 1) * 16, 72);
                }
            }
            #pragma unroll
            for (int mt = 0; mt < 4; mt++) {
                #pragma unroll
                for (int nt = 0; nt < 4; nt++) {
                    wmma::mma_sync(acc[mt][nt], af[cur][mt], bf[cur][nt], acc[mt][nt]);
                }
            }
        }
        __syncthreads();
    }

    // direct-from-fragment epilogue with bias
    const int r0e = lane >> 2;
    const int cce = 2 * (lane & 3);
    #pragma unroll
    for (int mt = 0; mt < 4; mt++) {
        const int g0 = m0 + wm * 64 + mt * 16 + r0e;
        const int g1 = g0 + 8;
        #pragma unroll
        for (int nt = 0; nt < 4; nt++) {
            const float* x = acc[mt][nt].x;
            const int colA = n0 + wn * 64 + nt * 16 + cce;
            const float bA0 = __ldg(&bias[colA]);
            const float bA1 = __ldg(&bias[colA + 1]);
            const float bB0 = __ldg(&bias[colA + 8]);
            const float bB1 = __ldg(&bias[colA + 9]);
            float2 o;
            o.x = x[0] + bA0; o.y = x[1] + bA1;
            *(float2*)&outp[(size_t)g0 * Cq + colA] = o;
            o.x = x[2] + bA0; o.y = x[3] + bA1;
            *(float2*)&outp[(size_t)g1 * Cq + colA] = o;
            o.x = x[4] + bB0; o.y = x[5] + bB1;
            *(float2*)&outp[(size_t)g0 * Cq + colA + 8] = o;
            o.x = x[6] + bB0; o.y = x[7] + bB1;
            *(float2*)&outp[(size_t)g1 * Cq + colA + 8] = o;
        }
    }
}

// ---------------- K/V staging (cp.async, one 64-row block, 128 threads) ----
__device__ __forceinline__ void stage_kv_async(
    __half* kd, __half* vd, const __half* Kg, const __half* Vg, int kb, int tid)
{
    #pragma unroll
    for (int i = 0; i < 4; i++) {
        const int c = tid + 128 * i;
        const int row = c >> 3;
        const int cq = c & 7;
        __pipeline_memcpy_async(kd + row * 72 + cq * 8,
                                Kg + (size_t)(kb + row) * HDq + cq * 8, 16);
        __pipeline_memcpy_async(vd + row * 72 + cq * 8,
                                Vg + (size_t)(kb + row) * HDq + cq * 8, 16);
    }
}

// ---------------- wmma flash attention (register softmax, O in fragments) --
__global__ __launch_bounds__(128) void attn_w(
    const int* __restrict__ pad, const int* __restrict__ cs_ptr)
{
    extern __shared__ __align__(16) char dsm[];
    __half* kbuf = (__half*)dsm;
    __half* vbuf = kbuf + 2 * 4608;
    __half* pst  = vbuf + 2 * 4608;
    float*  padf = (float*)(pst + 4 * 1280);
    int*    padcnt = (int*)(padf + 2 * 64);

    const int b  = blockIdx.z;
    const int h  = blockIdx.y;
    const int q0 = ((int)gridDim.x - 1 - (int)blockIdx.x) * 64;
    const int tid  = threadIdx.x;
    const int lane = tid & 31;
    const int w    = tid >> 5;
    const int cs   = *cs_ptr;

    const __half* Qg = g_qh + (((size_t)b * Hq + h) * Nq) * HDq;
    const __half* Kg = g_kh + (((size_t)b * Hq + h) * Nq) * HDq;
    const __half* Vg = g_vh + (((size_t)b * Hq + h) * Nq) * HDq;

    __half* qstage = pst;
    #pragma unroll
    for (int i = 0; i < 4; i++) {
        const int c = tid + 128 * i;
        const int row = c >> 3;
        const int cq = c & 7;
        *(uint4*)&qstage[row * 72 + cq * 8] =
            *(const uint4*)&Qg[(size_t)(q0 + row) * HDq + cq * 8];
    }
    __syncthreads();

    wmma::fragment<wmma::matrix_a, 16, 16, 16, __half, wmma::row_major> aQ[4];
    #pragma unroll
    for (int ks = 0; ks < 4; ks++) {
        wmma::load_matrix_sync(aQ[ks], &qstage[(w * 16) * 72 + ks * 16], 72);
    }
    __syncthreads();

    __half* pstw = pst + w * 1280;
    const int r0 = lane >> 2;
    const int r1 = r0 + 8;
    const int cc = 2 * (lane & 3);
    const int qi0 = q0 + w * 16 + r0;
    const int qi1 = q0 + w * 16 + r1;
    const float scale = 0.125f;

    wmma::fragment<wmma::accumulator, 16, 16, 16, float> ofrag[4];
    #pragma unroll
    for (int nt = 0; nt < 4; nt++) {
        wmma::fill_fragment(ofrag[nt], 0.0f);
    }
    float m0 = -1e30f, m1 = -1e30f;
    float l0 = 0.f, l1 = 0.f;

    int hiq = q0 + 64;
    if (cs > hiq) hiq = (cs < Nq) ? cs : Nq;
    const int nkb = (hiq + 63) >> 6;

    stage_kv_async(kbuf, vbuf, Kg, Vg, 0, tid);
    __pipeline_commit();
    if (tid < 64) {
        const int pv = __ldg(&pad[(size_t)b * Nq + tid]);
        padf[tid] = pv ? -1e30f : 0.f;
        const unsigned bm = __ballot_sync(0xffffffffu, pv != 0);
        if ((tid & 31) == 0) padcnt[tid >> 5] = __popc(bm);
    }

    for (int kbi = 0; kbi < nkb; kbi++) {
        const int buf = kbi & 1;
        const int kb = kbi * 64;

        if (kbi + 1 < nkb) {
            stage_kv_async(kbuf + (buf ^ 1) * 4608, vbuf + (buf ^ 1) * 4608,
                           Kg, Vg, kb + 64, tid);
            __pipeline_commit();
            if (tid < 64) {
                const int pv = __ldg(&pad[(size_t)b * Nq + kb + 64 + tid]);
                padf[(buf ^ 1) * 64 + tid] = pv ? -1e30f : 0.f;
                const unsigned bm = __ballot_sync(0xffffffffu, pv != 0);
                if ((tid & 31) == 0) padcnt[(buf ^ 1) * 2 + (tid >> 5)] = __popc(bm);
            }
            __pipeline_wait_prior(1);
        } else {
            __pipeline_wait_prior(0);
        }
        __syncthreads();

        const bool allpad = (padcnt[buf * 2] + padcnt[buf * 2 + 1]) == 64;
        if (!allpad) {
            const __half* ksm = kbuf + buf * 4608;
            const __half* vsm = vbuf + buf * 4608;
            const float* padfb = padf + buf * 64;

            wmma::fragment<wmma::accumulator, 16, 16, 16, float> sacc[4];
            #pragma unroll
            for (int nt = 0; nt < 4; nt++) {
                wmma::fill_fragment(sacc[nt], 0.0f);
                #pragma unroll
                for (int ks = 0; ks < 4; ks++) {
                    wmma::fragment<wmma::matrix_b, 16, 16, 16, __half, wmma::col_major> bK;
                    wmma::load_matrix_sync(bK, &ksm[(nt * 16) * 72 + ks * 16], 72);
                    wmma::mma_sync(sacc[nt], aQ[ks], bK, sacc[nt]);
                }
            }

            float tmax0 = -1e30f, tmax1 = -1e30f;
            #pragma unroll
            for (int nt = 0; nt < 4; nt++) {
                const int base = nt * 16;
                const int cA = kb + base + cc;
                const int cB = cA + 8;
                const float pA0 = padfb[base + cc];
                const float pA1 = padfb[base + cc + 1];
                const float pB0 = padfb[base + cc + 8];
                const float pB1 = padfb[base + cc + 9];
                float* x = sacc[nt].x;
                x[0] = ((cA     <= qi0) || (cA     < cs)) ? x[0] * scale + pA0 : -1e30f;
                x[1] = ((cA + 1 <= qi0) || (cA + 1 < cs)) ? x[1] * scale + pA1 : -1e30f;
                x[2] = ((cA     <= qi1) || (cA     < cs)) ? x[2] * scale + pA0 : -1e30f;
                x[3] = ((cA + 1 <= qi1) || (cA + 1 < cs)) ? x[3] * scale + pA1 : -1e30f;
                x[4] = ((cB     <= qi0) || (cB     < cs)) ? x[4] * scale + pB0 : -1e30f;
                x[5] = ((cB + 1 <= qi0) || (cB + 1 < cs)) ? x[5] * scale + pB1 : -1e30f;
                x[6] = ((cB     <= qi1) || (cB     < cs)) ? x[6] * scale + pB0 : -1e30f;
                x[7] = ((cB + 1 <= qi1) || (cB + 1 < cs)) ? x[7] * scale + pB1 : -1e30f;
                tmax0 = fmaxf(tmax0, fmaxf(fmaxf(x[0], x[1]), fmaxf(x[4], x[5])));
                tmax1 = fmaxf(tmax1, fmaxf(fmaxf(x[2], x[3]), fmaxf(x[6], x[7])));
            }
            tmax0 = fmaxf(tmax0, __shfl_xor_sync(0xffffffffu, tmax0, 1));
            tmax0 = fmaxf(tmax0, __shfl_xor_sync(0xffffffffu, tmax0, 2));
            tmax1 = fmaxf(tmax1, __shfl_xor_sync(0xffffffffu, tmax1, 1));
            tmax1 = fmaxf(tmax1, __shfl_xor_sync(0xffffffffu, tmax1, 2));

            const float mn0 = fmaxf(m0, tmax0);
            const float mn1 = fmaxf(m1, tmax1);
            const float corr0 = __expf(m0 - mn0);
            const float corr1 = __expf(m1 - mn1);
            m0 = mn0;
            m1 = mn1;

            float ls0 = 0.f, ls1 = 0.f;
            #pragma unroll
            for (int nt = 0; nt < 4; nt++) {
                float* x = sacc[nt].x;
                const float p0 = __expf(x[0] - mn0);
                const float p1 = __expf(x[1] - mn0);
                const float p2 = __expf(x[2] - mn1);
                const float p3 = __expf(x[3] - mn1);
                const float p4 = __expf(x[4] - mn0);
                const float p5 = __expf(x[5] - mn0);
                const float p6 = __expf(x[6] - mn1);
                const float p7 = __expf(x[7] - mn1);
                ls0 += (p0 + p1) + (p4 + p5);
                ls1 += (p2 + p3) + (p6 + p7);
                const int base = nt * 16 + cc;
                *(__half2*)&pstw[r0 * 80 + base]     = __floats2half2_rn(p0, p1);
                *(__half2*)&pstw[r1 * 80 + base]     = __floats2half2_rn(p2, p3);
                *(__half2*)&pstw[r0 * 80 + base + 8] = __floats2half2_rn(p4, p5);
                *(__half2*)&pstw[r1 * 80 + base + 8] = __floats2half2_rn(p6, p7);
            }
            ls0 += __shfl_xor_sync(0xffffffffu, ls0, 1);
            ls0 += __shfl_xor_sync(0xffffffffu, ls0, 2);
            ls1 += __shfl_xor_sync(0xffffffffu, ls1, 1);
            ls1 += __shfl_xor_sync(0xffffffffu, ls1, 2);
            l0 = l0 * corr0 + ls0;
            l1 = l1 * corr1 + ls1;

            __syncwarp();

            wmma::fragment<wmma::matrix_a, 16, 16, 16, __half, wmma::row_major> aP[4];
            #pragma unroll
            for (int ks = 0; ks < 4; ks++) {
                wmma::load_matrix_sync(aP[ks], pstw + ks * 16, 80);
            }

            #pragma unroll
            for (int nt = 0; nt < 4; nt++) {
                float* x = ofrag[nt].x;
                x[0] *= corr0; x[1] *= corr0; x[4] *= corr0; x[5] *= corr0;
                x[2] *= corr1; x[3] *= corr1; x[6] *= corr1; x[7] *= corr1;
            }
            #pragma unroll
            for (int ks = 0; ks < 4; ks++) {
                #pragma unroll
                for (int nt = 0; nt < 4; nt++) {
                    wmma::fragment<wmma::matrix_b, 16, 16, 16, __half, wmma::row_major> bV;
                    wmma::load_matrix_sync(bV, &vsm[(ks * 16) * 72 + nt * 16], 72);
                    wmma::mma_sync(ofrag[nt], aP[ks], bV, ofrag[nt]);
                }
            }
        }
        __syncthreads();
    }

    const float inv0 = 1.f / l0;
    const float inv1 = 1.f / l1;
    __half* out0 = g_atth + ((size_t)b * Nq + qi0) * Cq + h * HDq;
    __half* out1 = g_atth + ((size_t)b * Nq + qi1) * Cq + h * HDq;
    #pragma unroll
    for (int nt = 0; nt < 4; nt++) {
        const float* x = ofrag[nt].x;
        const int col = nt * 16 + cc;
        *(__half2*)&out0[col]     = __floats2half2_rn(x[0] * inv0, x[1] * inv0);
        *(__half2*)&out1[col]     = __floats2half2_rn(x[2] * inv1, x[3] * inv1);
        *(__half2*)&out0[col + 8] = __floats2half2_rn(x[4] * inv0, x[5] * inv0);
        *(__half2*)&out1[col + 8] = __floats2half2_rn(x[6] * inv1, x[7] * inv1);
    }
}

// ---------------- launch ----------------
extern "C" void kernel_launch(void* const* d_in, const int* in_sizes, int n_in,
                              void* d_out, int out_size) {
    const float* x      = (const float*)d_in[0];
    const int*   pad    = (const int*)d_in[1];
    const int*   cs     = (const int*)d_in[2];
    const float* w_qkv  = (const float*)d_in[3];
    const float* w_proj = (const float*)d_in[4];
    const float* b_proj = (const float*)d_in[5];

    float* out     = (float*)d_out;
    float* present = out + (size_t)Bq * Nq * Cq;

    __half* xh;     cudaGetSymbolAddress((void**)&xh, g_xh);
    __half* wqkvh;  cudaGetSymbolAddress((void**)&wqkvh, g_wqkvh);
    __half* wprojh; cudaGetSymbolAddress((void**)&wprojh, g_wprojh);
    __half* atth;   cudaGetSymbolAddress((void**)&atth, g_atth);

    const int gemm_smem = 2 * (2 * GSTG) * 2;                                 // 73728 B
    const int attn_smem = 4 * 4608 * 2 + 4 * 1280 * 2 + 2 * 64 * 4 + 16;      // 47632 B
    cudaFuncSetAttribute(gemm_qkv_w, cudaFuncAttributeMaxDynamicSharedMemorySize, gemm_smem);
    cudaFuncSetAttribute(gemm_proj_w, cudaFuncAttributeMaxDynamicSharedMemorySize, gemm_smem);
    cudaFuncSetAttribute(attn_w, cudaFuncAttributeMaxDynamicSharedMemorySize, attn_smem);

    {
        const int na4 = (Bq * Nq * Cq) / 4;
        const int nb4 = (N3q * Cq) / 4;
        const int nc4 = (Cq * Cq) / 4;
        const int tot = na4 + nb4 + nc4;
        cvt3_kernel<<<(tot + 255) / 256, 256>>>(x, xh, na4, w_qkv, wqkvh, nb4,
                                                w_proj, wprojh, nc4);
    }
    {
        dim3 grid(N3q / 128, (Bq * Nq) / 128);
        gemm_qkv_w<<<grid, 128, gemm_smem>>>(xh, wqkvh, present);
    }
    {
        dim3 grid(Nq / 64, Hq, Bq);
        attn_w<<<grid, 128, attn_smem>>>(pad, cs);
    }
    {
        dim3 grid(Cq / 128, (Bq * Nq) / 128);
        gemm_proj_w<<<grid, 128, gemm_smem>>>(atth, wprojh, b_proj, out);
    }
}